// round 14
// baseline (speedup 1.0000x reference)
#include <cuda_runtime.h>
#include <cuda_pipeline.h>
#include <math_constants.h>

#define BB 64
#define TT 4096
#define QDIM 1024
#define ADIM 256
#define MASK_VAL (-1e30f)

// Scratch (allocation-free rule: device globals)
__device__ float g_pq[BB * ADIM];        // processed query (B, AD)
__device__ float g_energies[BB * TT];    // masked energies (B, T)

__device__ __forceinline__ float tanh_fast(float x) {
    float y;
    asm("tanh.approx.f32 %0, %1;" : "=f"(y) : "f"(x));
    return y;
}

// ---------------------------------------------------------------------------
// Kernel 1: pq[b,d] = dot(query[b,:], Wq[d,:])   (64 x 256, K=1024)
// Tile (4 b x 8 d), 512 blocks, all co-resident. Frozen.
// ---------------------------------------------------------------------------
#define PQ_BT 4
__global__ void __launch_bounds__(256) pq_kernel(const float* __restrict__ query,
                                                 const float* __restrict__ Wq) {
    __shared__ float sq[PQ_BT * QDIM];             // 16 KB

    const int lane = threadIdx.x & 31;
    const int warp = threadIdx.x >> 5;             // 0..7
    const int btile = blockIdx.x >> 5;             // 0..15
    const int dtile = blockIdx.x & 31;             // 0..31
    const int b0 = btile * PQ_BT;
    const int d  = dtile * 8 + warp;

    const float4* w4 = reinterpret_cast<const float4*>(Wq + (size_t)d * QDIM);
    float4 w[8];
#pragma unroll
    for (int k = 0; k < 8; ++k) w[k] = w4[lane + 32 * k];

    {
        const float4* qg = reinterpret_cast<const float4*>(query + (size_t)b0 * QDIM);
        float4* sq4 = reinterpret_cast<float4*>(sq);
#pragma unroll
        for (int i = 0; i < 4; ++i)
            sq4[threadIdx.x + 256 * i] = qg[threadIdx.x + 256 * i];
    }
    __syncthreads();

    const float4* sq4 = reinterpret_cast<const float4*>(sq);
    float s[PQ_BT];
#pragma unroll
    for (int bi = 0; bi < PQ_BT; ++bi) s[bi] = 0.f;

#pragma unroll
    for (int k = 0; k < 8; ++k) {
#pragma unroll
        for (int bi = 0; bi < PQ_BT; ++bi) {
            float4 a = sq4[bi * 256 + lane + 32 * k];
            s[bi] += a.x * w[k].x + a.y * w[k].y + a.z * w[k].z + a.w * w[k].w;
        }
    }

#pragma unroll
    for (int off = 16; off > 0; off >>= 1) {
#pragma unroll
        for (int bi = 0; bi < PQ_BT; ++bi)
            s[bi] += __shfl_xor_sync(0xffffffffu, s[bi], off);
    }
    if (lane == 0) {
#pragma unroll
        for (int bi = 0; bi < PQ_BT; ++bi)
            g_pq[(b0 + bi) * ADIM + d] = s[bi];
    }
}

// ---------------------------------------------------------------------------
// Kernel 2: energies[b,t] = sum_d tanh(pq[b,d] + pm[b,t,d]) * v[d]; mask.
// One warp per 16 t-rows; masked rows (~50%) skipped.
// NEW: cp.async (LDGSTS) 3-STAGE smem pipeline. Depth-1 register pipelining
// kept only ~16 KB/SM in flight (< the ~25 KB Little's-law requirement ->
// measured 4.2 TB/s plateau). cp.async holds up to 3 row-pair stages
// (2 KB each) per warp in flight with ZERO register cost:
// ~128 KB/SM in flight -> DRAM-limited.
// Each lane consumes exactly the smem bytes it copied itself (no syncwarp).
// Empty commit groups pad the tail so wait_prior(STAGES-1) is constant.
// PDL: mask phase + stage prefetches issue before GridDependencySynchronize.
// mask arrives as int32 (harness normalizes bool -> int32).
// ---------------------------------------------------------------------------
#define TPW 16           // t-rows per warp
#define K2_WARPS 8
#define STAGES 3

__global__ void __launch_bounds__(256) energies_kernel(
        const float* __restrict__ pm,
        const int* __restrict__ mask,
        const float* __restrict__ v) {
    // 8 warps x 3 stages x (2 rows x 256 floats) = 48 KB
    __shared__ float sbuf[K2_WARPS][STAGES][2 * ADIM];

    const int lane = threadIdx.x & 31;
    const int warp = threadIdx.x >> 5;
    const int gw = blockIdx.x * K2_WARPS + warp;   // global warp id
    const int warpsPerB = TT / TPW;                // 256
    const int b = gw / warpsPerB;
    const int t0 = (gw % warpsPerB) * TPW;
    const size_t base = (size_t)b * TT + t0;

    // ---- Phase A: independent of k1's output ----
    const int myMask = (lane < TPW) ? mask[base + lane] : 1;
    const unsigned bits = __ballot_sync(0xffffffffu, (lane < TPW) && (myMask == 0));

    if (lane < TPW && myMask)
        g_energies[base + lane] = MASK_VAL;

    const int n = __popc(bits);
    if (n == 0) {
        cudaGridDependencySynchronize();
        return;
    }

    const float4* v4 = reinterpret_cast<const float4*>(v);
    const float4 v0 = v4[lane], v1 = v4[lane + 32];

    const int nIter = (n + 1) >> 1;
    float* const wbuf0 = &sbuf[warp][0][0];

    // Issue stage k (row pair 2k, 2k+1 of the unmasked set) into the ring.
    // 4 x 16B cp.async per lane; lane later reads back exactly these bytes.
#define K2_ISSUE(K)                                                           \
    {                                                                         \
        const int k_ = (K);                                                   \
        const int j0_ = __fns(bits, 0, 2 * k_ + 1);                           \
        const int j1_ = (2 * k_ + 1 < n) ? __fns(bits, 0, 2 * k_ + 2) : j0_;  \
        float* d_ = wbuf0 + (k_ % STAGES) * (2 * ADIM);                       \
        const float* s0_ = pm + (base + j0_) * ADIM;                          \
        const float* s1_ = pm + (base + j1_) * ADIM;                          \
        __pipeline_memcpy_async(d_ + 4 * lane,             s0_ + 4 * lane, 16);\
        __pipeline_memcpy_async(d_ + 128 + 4 * lane,       s0_ + 128 + 4 * lane, 16);\
        __pipeline_memcpy_async(d_ + 256 + 4 * lane,       s1_ + 4 * lane, 16);\
        __pipeline_memcpy_async(d_ + 384 + 4 * lane,       s1_ + 128 + 4 * lane, 16);\
        __pipeline_commit();                                                  \
    }

    // Prologue: fill the ring (pm-only; overlaps k1 via PDL).
#pragma unroll
    for (int k = 0; k < STAGES; ++k) {
        if (k < nIter) { K2_ISSUE(k) }
        else           { __pipeline_commit(); }    // empty group keeps count
    }

    // ---- Wait for k1 (g_pq) ----
    cudaGridDependencySynchronize();

    const float4* pq4 = reinterpret_cast<const float4*>(g_pq + b * ADIM);
    const float4 p0 = pq4[lane], p1 = pq4[lane + 32];

    for (int it = 0; it < nIter; ++it) {
        __pipeline_wait_prior(STAGES - 1);         // stage `it` complete

        const float* d = wbuf0 + (it % STAGES) * (2 * ADIM);
        const float4 A0 = *reinterpret_cast<const float4*>(d + 4 * lane);
        const float4 C0 = *reinterpret_cast<const float4*>(d + 128 + 4 * lane);
        const float4 A1 = *reinterpret_cast<const float4*>(d + 256 + 4 * lane);
        const float4 C1 = *reinterpret_cast<const float4*>(d + 384 + 4 * lane);

        // Refill the ring (one commit per iteration keeps accounting exact).
        {
            const int k = it + STAGES;
            if (k < nIter) { K2_ISSUE(k) }
            else           { __pipeline_commit(); }
        }

        float s0, s1;
        s0  = tanh_fast(A0.x + p0.x) * v0.x;
        s1  = tanh_fast(A1.x + p0.x) * v0.x;
        s0 += tanh_fast(A0.y + p0.y) * v0.y;
        s1 += tanh_fast(A1.y + p0.y) * v0.y;
        s0 += tanh_fast(A0.z + p0.z) * v0.z;
        s1 += tanh_fast(A1.z + p0.z) * v0.z;
        s0 += tanh_fast(A0.w + p0.w) * v0.w;
        s1 += tanh_fast(A1.w + p0.w) * v0.w;
        s0 += tanh_fast(C0.x + p1.x) * v1.x;
        s1 += tanh_fast(C1.x + p1.x) * v1.x;
        s0 += tanh_fast(C0.y + p1.y) * v1.y;
        s1 += tanh_fast(C1.y + p1.y) * v1.y;
        s0 += tanh_fast(C0.z + p1.z) * v1.z;
        s1 += tanh_fast(C1.z + p1.z) * v1.z;
        s0 += tanh_fast(C0.w + p1.w) * v1.w;
        s1 += tanh_fast(C1.w + p1.w) * v1.w;

#pragma unroll
        for (int off = 16; off > 0; off >>= 1) {
            s0 += __shfl_xor_sync(0xffffffffu, s0, off);
            s1 += __shfl_xor_sync(0xffffffffu, s1, off);
        }

        if (lane == 0) {
            const int j = it * 2;
            const int ci0 = __fns(bits, 0, j + 1);
            g_energies[base + ci0] = s0;
            if (j + 1 < n) {
                const int ci1 = __fns(bits, 0, j + 2);
                g_energies[base + ci1] = s1;
            }
        }
    }
    __pipeline_wait_prior(0);                      // drain before exit
#undef K2_ISSUE
}

// ---------------------------------------------------------------------------
// Kernel 3: row softmax over T=4096. One block (1024 thr) per batch row.
// Single-pass (shift-free): energies bounded, masked -1e30 -> exp = 0.
// ---------------------------------------------------------------------------
__global__ void __launch_bounds__(1024) softmax_kernel(float* __restrict__ out) {
    const int b = blockIdx.x;
    const int tid = threadIdx.x;
    const int lane = tid & 31;
    const int warp = tid >> 5;
    __shared__ float red[32];
    __shared__ float bcast;

    float e[4];
    float s = 0.f;
#pragma unroll
    for (int i = 0; i < 4; ++i) {
        e[i] = __expf(g_energies[(size_t)b * TT + i * 1024 + tid]);
        s += e[i];
    }
#pragma unroll
    for (int off = 16; off > 0; off >>= 1)
        s += __shfl_xor_sync(0xffffffffu, s, off);
    if (lane == 0) red[warp] = s;
    __syncthreads();
    if (warp == 0) {
        float ss = red[lane];
#pragma unroll
        for (int off = 16; off > 0; off >>= 1)
            ss += __shfl_xor_sync(0xffffffffu, ss, off);
        if (lane == 0) bcast = ss;
    }
    __syncthreads();
    const float inv = 1.0f / bcast;

#pragma unroll
    for (int i = 0; i < 4; ++i)
        out[(size_t)b * TT + i * 1024 + tid] = e[i] * inv;
}

// ---------------------------------------------------------------------------
extern "C" void kernel_launch(void* const* d_in, const int* in_sizes, int n_in,
                              void* d_out, int out_size) {
    const float* query = (const float*)d_in[0];          // (64, 1024) f32
    const float* pm    = (const float*)d_in[1];          // (64, 4096, 256) f32
    const int*   mask  = (const int*)d_in[2];            // (64, 4096) bool -> int32
    const float* Wq    = (const float*)d_in[3];          // (256, 1024) f32
    const float* v     = (const float*)d_in[4];          // (256,) f32
    float* out = (float*)d_out;                          // (64, 4096) f32

    // K1: 512 blocks, 256 threads
    pq_kernel<<<512, 256>>>(query, Wq);

    // K2 with PDL: mask phase + cp.async prologue overlap k1.
    {
        cudaLaunchConfig_t cfg = {};
        cfg.gridDim = dim3(2048);
        cfg.blockDim = dim3(256);
        cfg.dynamicSmemBytes = 0;
        cfg.stream = 0;
        cudaLaunchAttribute attrs[1];
        attrs[0].id = cudaLaunchAttributeProgrammaticStreamSerialization;
        attrs[0].val.programmaticStreamSerializationAllowed = 1;
        cfg.attrs = attrs;
        cfg.numAttrs = 1;
        cudaLaunchKernelEx(&cfg, energies_kernel, pm, mask, v);
    }

    // K3: one block per batch row
    softmax_kernel<<<BB, 1024>>>(out);
}

// round 15
// speedup vs baseline: 1.1655x; 1.1655x over previous
#include <cuda_runtime.h>
#include <math_constants.h>

#define BB 64
#define TT 4096
#define QDIM 1024
#define ADIM 256
#define MASK_VAL (-1e30f)

// Scratch (allocation-free rule: device globals)
__device__ float g_pq[BB * ADIM];        // processed query (B, AD)
__device__ float g_energies[BB * TT];    // masked energies (B, T)

__device__ __forceinline__ float tanh_fast(float x) {
    float y;
    asm("tanh.approx.f32 %0, %1;" : "=f"(y) : "f"(x));
    return y;
}

// ---------------------------------------------------------------------------
// Kernel 1: pq[b,d] = dot(query[b,:], Wq[d,:])   (64 x 256, K=1024)
// Tile (4 b x 8 d), 512 blocks, all co-resident. Frozen.
// ---------------------------------------------------------------------------
#define PQ_BT 4
__global__ void __launch_bounds__(256) pq_kernel(const float* __restrict__ query,
                                                 const float* __restrict__ Wq) {
    __shared__ float sq[PQ_BT * QDIM];             // 16 KB

    const int lane = threadIdx.x & 31;
    const int warp = threadIdx.x >> 5;             // 0..7
    const int btile = blockIdx.x >> 5;             // 0..15
    const int dtile = blockIdx.x & 31;             // 0..31
    const int b0 = btile * PQ_BT;
    const int d  = dtile * 8 + warp;

    const float4* w4 = reinterpret_cast<const float4*>(Wq + (size_t)d * QDIM);
    float4 w[8];
#pragma unroll
    for (int k = 0; k < 8; ++k) w[k] = w4[lane + 32 * k];

    {
        const float4* qg = reinterpret_cast<const float4*>(query + (size_t)b0 * QDIM);
        float4* sq4 = reinterpret_cast<float4*>(sq);
#pragma unroll
        for (int i = 0; i < 4; ++i)
            sq4[threadIdx.x + 256 * i] = qg[threadIdx.x + 256 * i];
    }
    __syncthreads();

    const float4* sq4 = reinterpret_cast<const float4*>(sq);
    float s[PQ_BT];
#pragma unroll
    for (int bi = 0; bi < PQ_BT; ++bi) s[bi] = 0.f;

#pragma unroll
    for (int k = 0; k < 8; ++k) {
#pragma unroll
        for (int bi = 0; bi < PQ_BT; ++bi) {
            float4 a = sq4[bi * 256 + lane + 32 * k];
            s[bi] += a.x * w[k].x + a.y * w[k].y + a.z * w[k].z + a.w * w[k].w;
        }
    }

#pragma unroll
    for (int off = 16; off > 0; off >>= 1) {
#pragma unroll
        for (int bi = 0; bi < PQ_BT; ++bi)
            s[bi] += __shfl_xor_sync(0xffffffffu, s[bi], off);
    }
    if (lane == 0) {
#pragma unroll
        for (int bi = 0; bi < PQ_BT; ++bi)
            g_pq[(b0 + bi) * ADIM + d] = s[bi];
    }
}

// ---------------------------------------------------------------------------
// Kernel 2: energies[b,t] = sum_d tanh(pq[b,d] + pm[b,t,d]) * v[d]; mask.
// EXACT R13 per-warp structure (best measured; cp.async/depth-2/occupancy
// experiments all regressed or were flat -> this pattern is at its
// masked-gather DRAM floor). ONLY change: 128-thread blocks (4 warps) ->
// finer CTA retire granularity, smoothing the binomial per-warp work
// variance at the last wave.
// pm read with __ldcs (streaming); mask arrives as int32.
// ---------------------------------------------------------------------------
#define TPW 16           // t-rows per warp
#define K2_WARPS 4       // warps per block (128 threads)
__global__ void __launch_bounds__(128, 8) energies_kernel(
        const float* __restrict__ pm,
        const int* __restrict__ mask,
        const float* __restrict__ v) {
    const int lane = threadIdx.x & 31;
    const int warp = threadIdx.x >> 5;
    const int gw = blockIdx.x * K2_WARPS + warp;   // global warp id
    const int warpsPerB = TT / TPW;                // 256
    const int b = gw / warpsPerB;
    const int t0 = (gw % warpsPerB) * TPW;
    const size_t base = (size_t)b * TT + t0;

    // ---- Phase A: independent of k1's output ----
    const int myMask = (lane < TPW) ? mask[base + lane] : 1;
    const unsigned bits = __ballot_sync(0xffffffffu, (lane < TPW) && (myMask == 0));

    if (lane < TPW && myMask)
        g_energies[base + lane] = MASK_VAL;

    const int n = __popc(bits);
    if (n == 0) {
        cudaGridDependencySynchronize();
        return;
    }

    const float4* v4 = reinterpret_cast<const float4*>(v);
    const float4 v0 = v4[lane], v1 = v4[lane + 32];

    const int nIter = (n + 1) >> 1;

    // Prologue pm loads (indices depend only on mask).
    int i0 = __fns(bits, 0, 1);
    int i1 = (n > 1) ? __fns(bits, 0, 2) : i0;
    const float4* x0 = reinterpret_cast<const float4*>(pm + (base + i0) * ADIM);
    const float4* x1 = reinterpret_cast<const float4*>(pm + (base + i1) * ADIM);
    float4 a0 = __ldcs(x0 + lane);
    float4 c0 = __ldcs(x0 + lane + 32);
    float4 a1 = __ldcs(x1 + lane);
    float4 c1 = __ldcs(x1 + lane + 32);

    // ---- Wait for k1 (g_pq) ----
    cudaGridDependencySynchronize();

    const float4* pq4 = reinterpret_cast<const float4*>(g_pq + b * ADIM);
    const float4 p0 = pq4[lane], p1 = pq4[lane + 32];

    for (int it = 0; it < nIter; ++it) {
        const int j = it * 2;
        const bool has1 = (j + 1 < n);
        const int ci0 = i0, ci1 = i1;
        const float4 A0 = a0, C0 = c0, A1 = a1, C1 = c1;

        // Prefetch next pair before the reduce chain of the current pair.
        if (it + 1 < nIter) {
            const int jn = j + 2;
            i0 = __fns(bits, 0, jn + 1);
            i1 = (jn + 1 < n) ? __fns(bits, 0, jn + 2) : i0;
            const float4* y0 = reinterpret_cast<const float4*>(pm + (base + i0) * ADIM);
            const float4* y1 = reinterpret_cast<const float4*>(pm + (base + i1) * ADIM);
            a0 = __ldcs(y0 + lane);
            c0 = __ldcs(y0 + lane + 32);
            a1 = __ldcs(y1 + lane);
            c1 = __ldcs(y1 + lane + 32);
        }

        float s0, s1;
        s0  = tanh_fast(A0.x + p0.x) * v0.x;
        s1  = tanh_fast(A1.x + p0.x) * v0.x;
        s0 += tanh_fast(A0.y + p0.y) * v0.y;
        s1 += tanh_fast(A1.y + p0.y) * v0.y;
        s0 += tanh_fast(A0.z + p0.z) * v0.z;
        s1 += tanh_fast(A1.z + p0.z) * v0.z;
        s0 += tanh_fast(A0.w + p0.w) * v0.w;
        s1 += tanh_fast(A1.w + p0.w) * v0.w;
        s0 += tanh_fast(C0.x + p1.x) * v1.x;
        s1 += tanh_fast(C1.x + p1.x) * v1.x;
        s0 += tanh_fast(C0.y + p1.y) * v1.y;
        s1 += tanh_fast(C1.y + p1.y) * v1.y;
        s0 += tanh_fast(C0.z + p1.z) * v1.z;
        s1 += tanh_fast(C1.z + p1.z) * v1.z;
        s0 += tanh_fast(C0.w + p1.w) * v1.w;
        s1 += tanh_fast(C1.w + p1.w) * v1.w;

#pragma unroll
        for (int off = 16; off > 0; off >>= 1) {
            s0 += __shfl_xor_sync(0xffffffffu, s0, off);
            s1 += __shfl_xor_sync(0xffffffffu, s1, off);
        }

        if (lane == 0) {
            g_energies[base + ci0] = s0;
            if (has1) g_energies[base + ci1] = s1;
        }
    }
}

// ---------------------------------------------------------------------------
// Kernel 3: row softmax over T=4096. One block (1024 thr) per batch row.
// Single-pass (shift-free): energies bounded, masked -1e30 -> exp = 0.
// ---------------------------------------------------------------------------
__global__ void __launch_bounds__(1024) softmax_kernel(float* __restrict__ out) {
    const int b = blockIdx.x;
    const int tid = threadIdx.x;
    const int lane = tid & 31;
    const int warp = tid >> 5;
    __shared__ float red[32];
    __shared__ float bcast;

    float e[4];
    float s = 0.f;
#pragma unroll
    for (int i = 0; i < 4; ++i) {
        e[i] = __expf(g_energies[(size_t)b * TT + i * 1024 + tid]);
        s += e[i];
    }
#pragma unroll
    for (int off = 16; off > 0; off >>= 1)
        s += __shfl_xor_sync(0xffffffffu, s, off);
    if (lane == 0) red[warp] = s;
    __syncthreads();
    if (warp == 0) {
        float ss = red[lane];
#pragma unroll
        for (int off = 16; off > 0; off >>= 1)
            ss += __shfl_xor_sync(0xffffffffu, ss, off);
        if (lane == 0) bcast = ss;
    }
    __syncthreads();
    const float inv = 1.0f / bcast;

#pragma unroll
    for (int i = 0; i < 4; ++i)
        out[(size_t)b * TT + i * 1024 + tid] = e[i] * inv;
}

// ---------------------------------------------------------------------------
extern "C" void kernel_launch(void* const* d_in, const int* in_sizes, int n_in,
                              void* d_out, int out_size) {
    const float* query = (const float*)d_in[0];          // (64, 1024) f32
    const float* pm    = (const float*)d_in[1];          // (64, 4096, 256) f32
    const int*   mask  = (const int*)d_in[2];            // (64, 4096) bool -> int32
    const float* Wq    = (const float*)d_in[3];          // (256, 1024) f32
    const float* v     = (const float*)d_in[4];          // (256,) f32
    float* out = (float*)d_out;                          // (64, 4096) f32

    // K1: 512 blocks, 256 threads
    pq_kernel<<<512, 256>>>(query, Wq);

    // K2 with PDL (neutral but harmless; kept for comparability).
    // 4096 blocks x 128 threads (same 16384 warps as before).
    {
        cudaLaunchConfig_t cfg = {};
        cfg.gridDim = dim3(4096);
        cfg.blockDim = dim3(128);
        cfg.dynamicSmemBytes = 0;
        cfg.stream = 0;
        cudaLaunchAttribute attrs[1];
        attrs[0].id = cudaLaunchAttributeProgrammaticStreamSerialization;
        attrs[0].val.programmaticStreamSerializationAllowed = 1;
        cfg.attrs = attrs;
        cfg.numAttrs = 1;
        cudaLaunchKernelEx(&cfg, energies_kernel, pm, mask, v);
    }

    // K3: one block per batch row
    softmax_kernel<<<BB, 1024>>>(out);
}

// round 16
// speedup vs baseline: 1.1739x; 1.0072x over previous
#include <cuda_runtime.h>
#include <math_constants.h>

#define BB 64
#define TT 4096
#define QDIM 1024
#define ADIM 256
#define MASK_VAL (-1e30f)

// Scratch (allocation-free rule: device globals)
__device__ float g_pq[BB * ADIM];        // processed query (B, AD)
__device__ float g_energies[BB * TT];    // masked energies (B, T)

__device__ __forceinline__ float tanh_fast(float x) {
    float y;
    asm("tanh.approx.f32 %0, %1;" : "=f"(y) : "f"(x));
    return y;
}

// ---------------------------------------------------------------------------
// Kernel 1: pq[b,d] = dot(query[b,:], Wq[d,:])   (64 x 256, K=1024)
// Tile (4 b x 8 d), 512 blocks, all co-resident. Frozen.
// ---------------------------------------------------------------------------
#define PQ_BT 4
__global__ void __launch_bounds__(256) pq_kernel(const float* __restrict__ query,
                                                 const float* __restrict__ Wq) {
    __shared__ float sq[PQ_BT * QDIM];             // 16 KB

    const int lane = threadIdx.x & 31;
    const int warp = threadIdx.x >> 5;             // 0..7
    const int btile = blockIdx.x >> 5;             // 0..15
    const int dtile = blockIdx.x & 31;             // 0..31
    const int b0 = btile * PQ_BT;
    const int d  = dtile * 8 + warp;

    const float4* w4 = reinterpret_cast<const float4*>(Wq + (size_t)d * QDIM);
    float4 w[8];
#pragma unroll
    for (int k = 0; k < 8; ++k) w[k] = w4[lane + 32 * k];

    {
        const float4* qg = reinterpret_cast<const float4*>(query + (size_t)b0 * QDIM);
        float4* sq4 = reinterpret_cast<float4*>(sq);
#pragma unroll
        for (int i = 0; i < 4; ++i)
            sq4[threadIdx.x + 256 * i] = qg[threadIdx.x + 256 * i];
    }
    __syncthreads();

    const float4* sq4 = reinterpret_cast<const float4*>(sq);
    float s[PQ_BT];
#pragma unroll
    for (int bi = 0; bi < PQ_BT; ++bi) s[bi] = 0.f;

#pragma unroll
    for (int k = 0; k < 8; ++k) {
#pragma unroll
        for (int bi = 0; bi < PQ_BT; ++bi) {
            float4 a = sq4[bi * 256 + lane + 32 * k];
            s[bi] += a.x * w[k].x + a.y * w[k].y + a.z * w[k].z + a.w * w[k].w;
        }
    }

#pragma unroll
    for (int off = 16; off > 0; off >>= 1) {
#pragma unroll
        for (int bi = 0; bi < PQ_BT; ++bi)
            s[bi] += __shfl_xor_sync(0xffffffffu, s[bi], off);
    }
    if (lane == 0) {
#pragma unroll
        for (int bi = 0; bi < PQ_BT; ++bi)
            g_pq[(b0 + bi) * ADIM + d] = s[bi];
    }
}

// ---------------------------------------------------------------------------
// Kernel 2: energies[b,t] = sum_d tanh(pq[b,d] + pm[b,t,d]) * v[d]; mask.
// R13 per-warp structure (masked-gather DRAM-floor pattern).
// R15 proved CTA retire granularity matters (-1.8 us going 8->4 warps);
// this round: 2-warp (64-thread) blocks, grid 8192 -> retire quantum
// halves again, more waves for work-steal tail smoothing.
// pm read with __ldcs (streaming); mask arrives as int32.
// ---------------------------------------------------------------------------
#define TPW 16           // t-rows per warp
#define K2_WARPS 2       // warps per block (64 threads)
__global__ void __launch_bounds__(64, 16) energies_kernel(
        const float* __restrict__ pm,
        const int* __restrict__ mask,
        const float* __restrict__ v) {
    const int lane = threadIdx.x & 31;
    const int warp = threadIdx.x >> 5;
    const int gw = blockIdx.x * K2_WARPS + warp;   // global warp id
    const int warpsPerB = TT / TPW;                // 256
    const int b = gw / warpsPerB;
    const int t0 = (gw % warpsPerB) * TPW;
    const size_t base = (size_t)b * TT + t0;

    // ---- Phase A: independent of k1's output ----
    const int myMask = (lane < TPW) ? mask[base + lane] : 1;
    const unsigned bits = __ballot_sync(0xffffffffu, (lane < TPW) && (myMask == 0));

    if (lane < TPW && myMask)
        g_energies[base + lane] = MASK_VAL;

    const int n = __popc(bits);
    if (n == 0) {
        cudaGridDependencySynchronize();
        return;
    }

    const float4* v4 = reinterpret_cast<const float4*>(v);
    const float4 v0 = v4[lane], v1 = v4[lane + 32];

    const int nIter = (n + 1) >> 1;

    // Prologue pm loads (indices depend only on mask).
    int i0 = __fns(bits, 0, 1);
    int i1 = (n > 1) ? __fns(bits, 0, 2) : i0;
    const float4* x0 = reinterpret_cast<const float4*>(pm + (base + i0) * ADIM);
    const float4* x1 = reinterpret_cast<const float4*>(pm + (base + i1) * ADIM);
    float4 a0 = __ldcs(x0 + lane);
    float4 c0 = __ldcs(x0 + lane + 32);
    float4 a1 = __ldcs(x1 + lane);
    float4 c1 = __ldcs(x1 + lane + 32);

    // ---- Wait for k1 (g_pq) ----
    cudaGridDependencySynchronize();

    const float4* pq4 = reinterpret_cast<const float4*>(g_pq + b * ADIM);
    const float4 p0 = pq4[lane], p1 = pq4[lane + 32];

    for (int it = 0; it < nIter; ++it) {
        const int j = it * 2;
        const bool has1 = (j + 1 < n);
        const int ci0 = i0, ci1 = i1;
        const float4 A0 = a0, C0 = c0, A1 = a1, C1 = c1;

        // Prefetch next pair before the reduce chain of the current pair.
        if (it + 1 < nIter) {
            const int jn = j + 2;
            i0 = __fns(bits, 0, jn + 1);
            i1 = (jn + 1 < n) ? __fns(bits, 0, jn + 2) : i0;
            const float4* y0 = reinterpret_cast<const float4*>(pm + (base + i0) * ADIM);
            const float4* y1 = reinterpret_cast<const float4*>(pm + (base + i1) * ADIM);
            a0 = __ldcs(y0 + lane);
            c0 = __ldcs(y0 + lane + 32);
            a1 = __ldcs(y1 + lane);
            c1 = __ldcs(y1 + lane + 32);
        }

        float s0, s1;
        s0  = tanh_fast(A0.x + p0.x) * v0.x;
        s1  = tanh_fast(A1.x + p0.x) * v0.x;
        s0 += tanh_fast(A0.y + p0.y) * v0.y;
        s1 += tanh_fast(A1.y + p0.y) * v0.y;
        s0 += tanh_fast(A0.z + p0.z) * v0.z;
        s1 += tanh_fast(A1.z + p0.z) * v0.z;
        s0 += tanh_fast(A0.w + p0.w) * v0.w;
        s1 += tanh_fast(A1.w + p0.w) * v0.w;
        s0 += tanh_fast(C0.x + p1.x) * v1.x;
        s1 += tanh_fast(C1.x + p1.x) * v1.x;
        s0 += tanh_fast(C0.y + p1.y) * v1.y;
        s1 += tanh_fast(C1.y + p1.y) * v1.y;
        s0 += tanh_fast(C0.z + p1.z) * v1.z;
        s1 += tanh_fast(C1.z + p1.z) * v1.z;
        s0 += tanh_fast(C0.w + p1.w) * v1.w;
        s1 += tanh_fast(C1.w + p1.w) * v1.w;

#pragma unroll
        for (int off = 16; off > 0; off >>= 1) {
            s0 += __shfl_xor_sync(0xffffffffu, s0, off);
            s1 += __shfl_xor_sync(0xffffffffu, s1, off);
        }

        if (lane == 0) {
            g_energies[base + ci0] = s0;
            if (has1) g_energies[base + ci1] = s1;
        }
    }
}

// ---------------------------------------------------------------------------
// Kernel 3: row softmax over T=4096. One block (1024 thr) per batch row.
// Single-pass (shift-free): energies bounded, masked -1e30 -> exp = 0.
// ---------------------------------------------------------------------------
__global__ void __launch_bounds__(1024) softmax_kernel(float* __restrict__ out) {
    const int b = blockIdx.x;
    const int tid = threadIdx.x;
    const int lane = tid & 31;
    const int warp = tid >> 5;
    __shared__ float red[32];
    __shared__ float bcast;

    float e[4];
    float s = 0.f;
#pragma unroll
    for (int i = 0; i < 4; ++i) {
        e[i] = __expf(g_energies[(size_t)b * TT + i * 1024 + tid]);
        s += e[i];
    }
#pragma unroll
    for (int off = 16; off > 0; off >>= 1)
        s += __shfl_xor_sync(0xffffffffu, s, off);
    if (lane == 0) red[warp] = s;
    __syncthreads();
    if (warp == 0) {
        float ss = red[lane];
#pragma unroll
        for (int off = 16; off > 0; off >>= 1)
            ss += __shfl_xor_sync(0xffffffffu, ss, off);
        if (lane == 0) bcast = ss;
    }
    __syncthreads();
    const float inv = 1.0f / bcast;

#pragma unroll
    for (int i = 0; i < 4; ++i)
        out[(size_t)b * TT + i * 1024 + tid] = e[i] * inv;
}

// ---------------------------------------------------------------------------
extern "C" void kernel_launch(void* const* d_in, const int* in_sizes, int n_in,
                              void* d_out, int out_size) {
    const float* query = (const float*)d_in[0];          // (64, 1024) f32
    const float* pm    = (const float*)d_in[1];          // (64, 4096, 256) f32
    const int*   mask  = (const int*)d_in[2];            // (64, 4096) bool -> int32
    const float* Wq    = (const float*)d_in[3];          // (256, 1024) f32
    const float* v     = (const float*)d_in[4];          // (256,) f32
    float* out = (float*)d_out;                          // (64, 4096) f32

    // K1: 512 blocks, 256 threads
    pq_kernel<<<512, 256>>>(query, Wq);

    // K2 with PDL. 8192 blocks x 64 threads (same 16384 warps).
    {
        cudaLaunchConfig_t cfg = {};
        cfg.gridDim = dim3(8192);
        cfg.blockDim = dim3(64);
        cfg.dynamicSmemBytes = 0;
        cfg.stream = 0;
        cudaLaunchAttribute attrs[1];
        attrs[0].id = cudaLaunchAttributeProgrammaticStreamSerialization;
        attrs[0].val.programmaticStreamSerializationAllowed = 1;
        cfg.attrs = attrs;
        cfg.numAttrs = 1;
        cudaLaunchKernelEx(&cfg, energies_kernel, pm, mask, v);
    }

    // K3: one block per batch row
    softmax_kernel<<<BB, 1024>>>(out);
}

// round 17
// speedup vs baseline: 1.1760x; 1.0018x over previous
#include <cuda_runtime.h>
#include <math_constants.h>

#define BB 64
#define TT 4096
#define QDIM 1024
#define ADIM 256
#define MASK_VAL (-1e30f)

// Scratch (allocation-free rule: device globals)
__device__ float g_pq[BB * ADIM];        // processed query (B, AD)
__device__ float g_energies[BB * TT];    // masked energies (B, T)

__device__ __forceinline__ float tanh_fast(float x) {
    float y;
    asm("tanh.approx.f32 %0, %1;" : "=f"(y) : "f"(x));
    return y;
}

// ---------------------------------------------------------------------------
// Kernel 1: pq[b,d] = dot(query[b,:], Wq[d,:])   (64 x 256, K=1024)
// Tile (4 b x 8 d), 512 blocks, all co-resident. Frozen.
// ---------------------------------------------------------------------------
#define PQ_BT 4
__global__ void __launch_bounds__(256) pq_kernel(const float* __restrict__ query,
                                                 const float* __restrict__ Wq) {
    __shared__ float sq[PQ_BT * QDIM];             // 16 KB

    const int lane = threadIdx.x & 31;
    const int warp = threadIdx.x >> 5;             // 0..7
    const int btile = blockIdx.x >> 5;             // 0..15
    const int dtile = blockIdx.x & 31;             // 0..31
    const int b0 = btile * PQ_BT;
    const int d  = dtile * 8 + warp;

    const float4* w4 = reinterpret_cast<const float4*>(Wq + (size_t)d * QDIM);
    float4 w[8];
#pragma unroll
    for (int k = 0; k < 8; ++k) w[k] = w4[lane + 32 * k];

    {
        const float4* qg = reinterpret_cast<const float4*>(query + (size_t)b0 * QDIM);
        float4* sq4 = reinterpret_cast<float4*>(sq);
#pragma unroll
        for (int i = 0; i < 4; ++i)
            sq4[threadIdx.x + 256 * i] = qg[threadIdx.x + 256 * i];
    }
    __syncthreads();

    const float4* sq4 = reinterpret_cast<const float4*>(sq);
    float s[PQ_BT];
#pragma unroll
    for (int bi = 0; bi < PQ_BT; ++bi) s[bi] = 0.f;

#pragma unroll
    for (int k = 0; k < 8; ++k) {
#pragma unroll
        for (int bi = 0; bi < PQ_BT; ++bi) {
            float4 a = sq4[bi * 256 + lane + 32 * k];
            s[bi] += a.x * w[k].x + a.y * w[k].y + a.z * w[k].z + a.w * w[k].w;
        }
    }

#pragma unroll
    for (int off = 16; off > 0; off >>= 1) {
#pragma unroll
        for (int bi = 0; bi < PQ_BT; ++bi)
            s[bi] += __shfl_xor_sync(0xffffffffu, s[bi], off);
    }
    if (lane == 0) {
#pragma unroll
        for (int bi = 0; bi < PQ_BT; ++bi)
            g_pq[(b0 + bi) * ADIM + d] = s[bi];
    }
}

// ---------------------------------------------------------------------------
// Kernel 2: energies[b,t] = sum_d tanh(pq[b,d] + pm[b,t,d]) * v[d]; mask.
// R13 per-warp structure (masked-gather DRAM-floor pattern).
// CTA retire-granularity endpoint: ONE warp per block (32 thr, grid 16384).
// R15/R16 measured -1.8 us (8->4 warps) and -0.26 us (4->2): geometric
// decay; this is the final notch (zero intra-CTA work-variance quantization,
// occupancy unchanged: 32 blocks/SM x 1 warp = same 32 resident warps).
// pm read with __ldcs (streaming); mask arrives as int32.
// ---------------------------------------------------------------------------
#define TPW 16           // t-rows per warp
__global__ void __launch_bounds__(32, 32) energies_kernel(
        const float* __restrict__ pm,
        const int* __restrict__ mask,
        const float* __restrict__ v) {
    const int lane = threadIdx.x & 31;
    const int gw = blockIdx.x;                     // one warp per block
    const int warpsPerB = TT / TPW;                // 256
    const int b = gw / warpsPerB;
    const int t0 = (gw % warpsPerB) * TPW;
    const size_t base = (size_t)b * TT + t0;

    // ---- Phase A: independent of k1's output ----
    const int myMask = (lane < TPW) ? mask[base + lane] : 1;
    const unsigned bits = __ballot_sync(0xffffffffu, (lane < TPW) && (myMask == 0));

    if (lane < TPW && myMask)
        g_energies[base + lane] = MASK_VAL;

    const int n = __popc(bits);
    if (n == 0) {
        cudaGridDependencySynchronize();
        return;
    }

    const float4* v4 = reinterpret_cast<const float4*>(v);
    const float4 v0 = v4[lane], v1 = v4[lane + 32];

    const int nIter = (n + 1) >> 1;

    // Prologue pm loads (indices depend only on mask).
    int i0 = __fns(bits, 0, 1);
    int i1 = (n > 1) ? __fns(bits, 0, 2) : i0;
    const float4* x0 = reinterpret_cast<const float4*>(pm + (base + i0) * ADIM);
    const float4* x1 = reinterpret_cast<const float4*>(pm + (base + i1) * ADIM);
    float4 a0 = __ldcs(x0 + lane);
    float4 c0 = __ldcs(x0 + lane + 32);
    float4 a1 = __ldcs(x1 + lane);
    float4 c1 = __ldcs(x1 + lane + 32);

    // ---- Wait for k1 (g_pq) ----
    cudaGridDependencySynchronize();

    const float4* pq4 = reinterpret_cast<const float4*>(g_pq + b * ADIM);
    const float4 p0 = pq4[lane], p1 = pq4[lane + 32];

    for (int it = 0; it < nIter; ++it) {
        const int j = it * 2;
        const bool has1 = (j + 1 < n);
        const int ci0 = i0, ci1 = i1;
        const float4 A0 = a0, C0 = c0, A1 = a1, C1 = c1;

        // Prefetch next pair before the reduce chain of the current pair.
        if (it + 1 < nIter) {
            const int jn = j + 2;
            i0 = __fns(bits, 0, jn + 1);
            i1 = (jn + 1 < n) ? __fns(bits, 0, jn + 2) : i0;
            const float4* y0 = reinterpret_cast<const float4*>(pm + (base + i0) * ADIM);
            const float4* y1 = reinterpret_cast<const float4*>(pm + (base + i1) * ADIM);
            a0 = __ldcs(y0 + lane);
            c0 = __ldcs(y0 + lane + 32);
            a1 = __ldcs(y1 + lane);
            c1 = __ldcs(y1 + lane + 32);
        }

        float s0, s1;
        s0  = tanh_fast(A0.x + p0.x) * v0.x;
        s1  = tanh_fast(A1.x + p0.x) * v0.x;
        s0 += tanh_fast(A0.y + p0.y) * v0.y;
        s1 += tanh_fast(A1.y + p0.y) * v0.y;
        s0 += tanh_fast(A0.z + p0.z) * v0.z;
        s1 += tanh_fast(A1.z + p0.z) * v0.z;
        s0 += tanh_fast(A0.w + p0.w) * v0.w;
        s1 += tanh_fast(A1.w + p0.w) * v0.w;
        s0 += tanh_fast(C0.x + p1.x) * v1.x;
        s1 += tanh_fast(C1.x + p1.x) * v1.x;
        s0 += tanh_fast(C0.y + p1.y) * v1.y;
        s1 += tanh_fast(C1.y + p1.y) * v1.y;
        s0 += tanh_fast(C0.z + p1.z) * v1.z;
        s1 += tanh_fast(C1.z + p1.z) * v1.z;
        s0 += tanh_fast(C0.w + p1.w) * v1.w;
        s1 += tanh_fast(C1.w + p1.w) * v1.w;

#pragma unroll
        for (int off = 16; off > 0; off >>= 1) {
            s0 += __shfl_xor_sync(0xffffffffu, s0, off);
            s1 += __shfl_xor_sync(0xffffffffu, s1, off);
        }

        if (lane == 0) {
            g_energies[base + ci0] = s0;
            if (has1) g_energies[base + ci1] = s1;
        }
    }
}

// ---------------------------------------------------------------------------
// Kernel 3: row softmax over T=4096. One block (1024 thr) per batch row.
// Single-pass (shift-free): energies bounded, masked -1e30 -> exp = 0.
// ---------------------------------------------------------------------------
__global__ void __launch_bounds__(1024) softmax_kernel(float* __restrict__ out) {
    const int b = blockIdx.x;
    const int tid = threadIdx.x;
    const int lane = tid & 31;
    const int warp = tid >> 5;
    __shared__ float red[32];
    __shared__ float bcast;

    float e[4];
    float s = 0.f;
#pragma unroll
    for (int i = 0; i < 4; ++i) {
        e[i] = __expf(g_energies[(size_t)b * TT + i * 1024 + tid]);
        s += e[i];
    }
#pragma unroll
    for (int off = 16; off > 0; off >>= 1)
        s += __shfl_xor_sync(0xffffffffu, s, off);
    if (lane == 0) red[warp] = s;
    __syncthreads();
    if (warp == 0) {
        float ss = red[lane];
#pragma unroll
        for (int off = 16; off > 0; off >>= 1)
            ss += __shfl_xor_sync(0xffffffffu, ss, off);
        if (lane == 0) bcast = ss;
    }
    __syncthreads();
    const float inv = 1.0f / bcast;

#pragma unroll
    for (int i = 0; i < 4; ++i)
        out[(size_t)b * TT + i * 1024 + tid] = e[i] * inv;
}

// ---------------------------------------------------------------------------
extern "C" void kernel_launch(void* const* d_in, const int* in_sizes, int n_in,
                              void* d_out, int out_size) {
    const float* query = (const float*)d_in[0];          // (64, 1024) f32
    const float* pm    = (const float*)d_in[1];          // (64, 4096, 256) f32
    const int*   mask  = (const int*)d_in[2];            // (64, 4096) bool -> int32
    const float* Wq    = (const float*)d_in[3];          // (256, 1024) f32
    const float* v     = (const float*)d_in[4];          // (256,) f32
    float* out = (float*)d_out;                          // (64, 4096) f32

    // K1: 512 blocks, 256 threads
    pq_kernel<<<512, 256>>>(query, Wq);

    // K2 with PDL. 16384 blocks x 32 threads (same 16384 warps).
    {
        cudaLaunchConfig_t cfg = {};
        cfg.gridDim = dim3(16384);
        cfg.blockDim = dim3(32);
        cfg.dynamicSmemBytes = 0;
        cfg.stream = 0;
        cudaLaunchAttribute attrs[1];
        attrs[0].id = cudaLaunchAttributeProgrammaticStreamSerialization;
        attrs[0].val.programmaticStreamSerializationAllowed = 1;
        cfg.attrs = attrs;
        cfg.numAttrs = 1;
        cudaLaunchKernelEx(&cfg, energies_kernel, pm, mask, v);
    }

    // K3: one block per batch row
    softmax_kernel<<<BB, 1024>>>(out);
}